// round 9
// baseline (speedup 1.0000x reference)
#include <cuda_runtime.h>
#include <cstdint>
#include <cstddef>

// Problem constants
#define NTOK   2048          // B*S
#define DMODEL 2048
#define DFF    8192
#define NEXP   4
#define CAP    2048          // worst-case tokens per expert
#define AS_STR 20            // padded row stride (floats) for ldmatrix A tiles

// ---------------------------------------------------------------------------
// Scratch (static device globals; no allocation anywhere)
// ---------------------------------------------------------------------------
__device__ int   g_cnt[NEXP];
__device__ int   g_list[NEXP * CAP];       // token index per (expert, slot)
__device__ int   g_tok_e[NTOK * 2];
__device__ int   g_tok_r[NTOK * 2];
__device__ float g_tok_v[NTOK * 2];
__device__ __align__(256) float g_H[(size_t)NEXP * CAP * DFF];     // 268 MB
__device__ __align__(256) float g_O[(size_t)NEXP * CAP * DMODEL];  //  67 MB

// ---------------------------------------------------------------------------
// TF32 / ldmatrix helpers
// ---------------------------------------------------------------------------
__device__ __forceinline__ unsigned f2tf(float x) {
    unsigned u;
    asm("cvt.rna.tf32.f32 %0, %1;" : "=r"(u) : "f"(x));
    return u;
}

__device__ __forceinline__ void mma_tf32(float* c, const unsigned* a, const unsigned* b) {
    asm volatile(
        "mma.sync.aligned.m16n8k8.row.col.f32.tf32.tf32.f32 "
        "{%0,%1,%2,%3}, {%4,%5,%6,%7}, {%8,%9}, {%0,%1,%2,%3};"
        : "+f"(c[0]), "+f"(c[1]), "+f"(c[2]), "+f"(c[3])
        : "r"(a[0]), "r"(a[1]), "r"(a[2]), "r"(a[3]), "r"(b[0]), "r"(b[1]));
}

// ldmatrix.x4 on tf32 data viewed as b16 pairs == exact tf32 A-fragment layout.
__device__ __forceinline__ void ldsm4(unsigned* r, unsigned addr) {
    asm volatile("ldmatrix.sync.aligned.m8n8.x4.shared.b16 {%0,%1,%2,%3}, [%4];"
        : "=r"(r[0]), "=r"(r[1]), "=r"(r[2]), "=r"(r[3]) : "r"(addr));
}

__device__ __forceinline__ unsigned smem_u32(const void* p) {
    return (unsigned)__cvta_generic_to_shared(p);
}

// ---------------------------------------------------------------------------
// Kernel 0: reset per-expert counters (runs every graph replay)
// ---------------------------------------------------------------------------
__global__ void init_kernel() {
    if (threadIdx.x < NEXP) g_cnt[threadIdx.x] = 0;
}

// ---------------------------------------------------------------------------
// Kernel 1: router
// ---------------------------------------------------------------------------
__global__ void router_kernel(const float* __restrict__ x, const float* __restrict__ Wr) {
    const int t = blockIdx.x;
    const float* xr = x + (size_t)t * DMODEL;

    float a0 = 0.f, a1 = 0.f, a2 = 0.f, a3 = 0.f;
    for (int d = threadIdx.x; d < DMODEL; d += 128) {
        float xv = xr[d];
        const float* w = Wr + d * NEXP;
        a0 += xv * w[0]; a1 += xv * w[1]; a2 += xv * w[2]; a3 += xv * w[3];
    }
    #pragma unroll
    for (int o = 16; o > 0; o >>= 1) {
        a0 += __shfl_xor_sync(0xffffffffu, a0, o);
        a1 += __shfl_xor_sync(0xffffffffu, a1, o);
        a2 += __shfl_xor_sync(0xffffffffu, a2, o);
        a3 += __shfl_xor_sync(0xffffffffu, a3, o);
    }
    __shared__ float red[4][NEXP];
    const int warp = threadIdx.x >> 5;
    if ((threadIdx.x & 31) == 0) {
        red[warp][0] = a0; red[warp][1] = a1; red[warp][2] = a2; red[warp][3] = a3;
    }
    __syncthreads();
    if (threadIdx.x == 0) {
        float l[NEXP];
        #pragma unroll
        for (int e = 0; e < NEXP; e++)
            l[e] = red[0][e] + red[1][e] + red[2][e] + red[3][e];
        float mx = l[0];
        #pragma unroll
        for (int e = 1; e < NEXP; e++) mx = fmaxf(mx, l[e]);
        float p[NEXP]; float s = 0.f;
        #pragma unroll
        for (int e = 0; e < NEXP; e++) { p[e] = __expf(l[e] - mx); s += p[e]; }
        float inv = 1.f / s;
        #pragma unroll
        for (int e = 0; e < NEXP; e++) p[e] *= inv;
        int e0 = 0;
        #pragma unroll
        for (int e = 1; e < NEXP; e++) if (p[e] > p[e0]) e0 = e;
        int e1 = (e0 == 0) ? 1 : 0;
        #pragma unroll
        for (int e = 0; e < NEXP; e++) if (e != e0 && p[e] > p[e1]) e1 = e;

        int s0 = atomicAdd(&g_cnt[e0], 1);
        g_list[e0 * CAP + s0] = t;
        g_tok_e[2*t + 0] = e0; g_tok_r[2*t + 0] = s0; g_tok_v[2*t + 0] = p[e0];

        int s1 = atomicAdd(&g_cnt[e1], 1);
        g_list[e1 * CAP + s1] = t;
        g_tok_e[2*t + 1] = e1; g_tok_r[2*t + 1] = s1; g_tok_v[2*t + 1] = p[e1];
    }
}

// ---------------------------------------------------------------------------
// Kernel 2: fused dual GEMM (g = X@Wg, u = X@Wu, H = silu(g)*u).
// Tile 128x64x16, 8 warps (4M x 2N), warp tile 32x32.
// 2-stage smem double buffer, tf32 converted at STS time, A via ldmatrix.
// mt is the FAST grid dim so concurrent blocks share B tiles through L2.
// ---------------------------------------------------------------------------
__global__ __launch_bounds__(256, 2) void gemm1_kernel(
    const float* __restrict__ x,
    const float* __restrict__ Wg,
    const float* __restrict__ Wu)
{
    const int e   = blockIdx.z;
    const int mt  = blockIdx.x;   // fastest
    const int nt  = blockIdx.y;
    const int cnt = g_cnt[e];
    if (mt * 128 >= cnt) return;

    __shared__ unsigned As[2][128 * AS_STR];   // [m][k] tf32, padded stride
    __shared__ unsigned BgS[2][16 * 68];       // [k][n] tf32
    __shared__ unsigned BuS[2][16 * 68];

    const int tid  = threadIdx.x;
    const int lane = tid & 31;
    const int warp = tid >> 5;
    const int gid  = lane >> 2;
    const int tig  = lane & 3;
    const int wmb  = (warp & 3) * 32;
    const int wnb  = (warp >> 2) * 32;

    // global load mapping
    const int am  = tid >> 2;            // rows am, am+64
    const int akc = (tid & 3) * 4;
    const int mg0 = mt * 128 + am;
    const int mg1 = mg0 + 64;
    const float* asrc0 = (mg0 < cnt) ? (x + (size_t)g_list[e*CAP + mg0] * DMODEL + akc) : nullptr;
    const float* asrc1 = (mg1 < cnt) ? (x + (size_t)g_list[e*CAP + mg1] * DMODEL + akc) : nullptr;

    const int bk = tid >> 4;             // 0..15
    const int bn = (tid & 15) * 4;
    const float* bgs = Wg + (size_t)e*DMODEL*DFF + (size_t)bk*DFF + (size_t)nt*64 + bn;
    const float* bus = Wu + (size_t)e*DMODEL*DFF + (size_t)bk*DFF + (size_t)nt*64 + bn;

    // ldmatrix per-lane byte offset: matrices [rows0-7|rows8-15] x [k0-3|k4-7]
    const unsigned a_lo = (((lane & 7) + ((lane >> 3) & 1) * 8) * AS_STR
                          + ((lane >> 4) << 2)) * 4u;
    const unsigned asb0 = smem_u32(&As[0][0]);
    const unsigned asb1 = smem_u32(&As[1][0]);

    float4 ra0, ra1, rbg, rbu;
    float cg[2][4][4], cu[2][4][4];
    #pragma unroll
    for (int i = 0; i < 2; i++)
        #pragma unroll
        for (int j = 0; j < 4; j++)
            #pragma unroll
            for (int r = 0; r < 4; r++) { cg[i][j][r] = 0.f; cu[i][j][r] = 0.f; }

#define G1_LOAD(kt) do {                                                               \
        ra0 = asrc0 ? *(const float4*)(asrc0 + (size_t)(kt)*16) : make_float4(0,0,0,0); \
        ra1 = asrc1 ? *(const float4*)(asrc1 + (size_t)(kt)*16) : make_float4(0,0,0,0); \
        rbg = *(const float4*)(bgs + (size_t)(kt)*16*DFF);                              \
        rbu = *(const float4*)(bus + (size_t)(kt)*16*DFF);                              \
    } while (0)
#define G1_STORE(s) do {                                                               \
        unsigned* Ad = As[s];                                                          \
        Ad[am*AS_STR + akc + 0] = f2tf(ra0.x); Ad[am*AS_STR + akc + 1] = f2tf(ra0.y);  \
        Ad[am*AS_STR + akc + 2] = f2tf(ra0.z); Ad[am*AS_STR + akc + 3] = f2tf(ra0.w);  \
        Ad[(am+64)*AS_STR + akc + 0] = f2tf(ra1.x);                                    \
        Ad[(am+64)*AS_STR + akc + 1] = f2tf(ra1.y);                                    \
        Ad[(am+64)*AS_STR + akc + 2] = f2tf(ra1.z);                                    \
        Ad[(am+64)*AS_STR + akc + 3] = f2tf(ra1.w);                                    \
        unsigned* Gd = &BgS[s][bk*68 + bn];                                            \
        Gd[0] = f2tf(rbg.x); Gd[1] = f2tf(rbg.y); Gd[2] = f2tf(rbg.z); Gd[3] = f2tf(rbg.w); \
        unsigned* Ud = &BuS[s][bk*68 + bn];                                            \
        Ud[0] = f2tf(rbu.x); Ud[1] = f2tf(rbu.y); Ud[2] = f2tf(rbu.z); Ud[3] = f2tf(rbu.w); \
    } while (0)

    G1_LOAD(0);
    G1_STORE(0);
    __syncthreads();

    const int NKT = DMODEL / 16;
    for (int kt = 0; kt < NKT; kt++) {
        if (kt + 1 < NKT) G1_LOAD(kt + 1);
        const int s = kt & 1;
        const unsigned asb = s ? asb1 : asb0;
        #pragma unroll
        for (int kk = 0; kk < 16; kk += 8) {
            unsigned a[2][4], bG[4][2], bU[4][2];
            const unsigned ab = asb + (unsigned)(wmb * (AS_STR*4)) + (unsigned)(kk*4) + a_lo;
            ldsm4(a[0], ab);
            ldsm4(a[1], ab + 16u * (AS_STR*4));
            #pragma unroll
            for (int nf = 0; nf < 4; nf++) {
                int nc = wnb + nf*8 + gid;
                bG[nf][0] = BgS[s][(kk+tig  )*68 + nc];
                bG[nf][1] = BgS[s][(kk+tig+4)*68 + nc];
                bU[nf][0] = BuS[s][(kk+tig  )*68 + nc];
                bU[nf][1] = BuS[s][(kk+tig+4)*68 + nc];
            }
            #pragma unroll
            for (int mf = 0; mf < 2; mf++)
                #pragma unroll
                for (int nf = 0; nf < 4; nf++) {
                    mma_tf32(cg[mf][nf], a[mf], bG[nf]);
                    mma_tf32(cu[mf][nf], a[mf], bU[nf]);
                }
        }
        if (kt + 1 < NKT) G1_STORE((kt + 1) & 1);
        __syncthreads();
    }

    // epilogue: H = silu(g) * u  (padded rows produce exactly 0)
    float* Hbase = g_H + ((size_t)e*CAP + (size_t)mt*128) * DFF + (size_t)nt*64;
    #pragma unroll
    for (int mf = 0; mf < 2; mf++) {
        #pragma unroll
        for (int nf = 0; nf < 4; nf++) {
            int r0 = wmb + mf*16 + gid;
            int c0 = wnb + nf*8 + tig*2;
            float* p0 = Hbase + (size_t)r0 * DFF + c0;
            float* p1 = Hbase + (size_t)(r0 + 8) * DFF + c0;
            float g0 = cg[mf][nf][0], g1 = cg[mf][nf][1];
            float g2 = cg[mf][nf][2], g3 = cg[mf][nf][3];
            p0[0] = (g0 / (1.f + __expf(-g0))) * cu[mf][nf][0];
            p0[1] = (g1 / (1.f + __expf(-g1))) * cu[mf][nf][1];
            p1[0] = (g2 / (1.f + __expf(-g2))) * cu[mf][nf][2];
            p1[1] = (g3 / (1.f + __expf(-g3))) * cu[mf][nf][3];
        }
    }
#undef G1_LOAD
#undef G1_STORE
}

// ---------------------------------------------------------------------------
// Kernel 3: O = H @ Wd[e].  Tile 128x128x16, 8 warps (2M x 4N), warp 64x32.
// ---------------------------------------------------------------------------
__global__ __launch_bounds__(256, 2) void gemm2_kernel(const float* __restrict__ Wd)
{
    const int e   = blockIdx.z;
    const int mt  = blockIdx.y;
    const int nt  = blockIdx.x;
    const int cnt = g_cnt[e];
    if (mt * 128 >= cnt) return;

    __shared__ unsigned As[2][128 * AS_STR];
    __shared__ unsigned Bs[2][16 * 132];

    const int tid  = threadIdx.x;
    const int lane = tid & 31;
    const int warp = tid >> 5;
    const int gid  = lane >> 2;
    const int tig  = lane & 3;
    const int wmb  = (warp & 1) * 64;
    const int wnb  = (warp >> 1) * 32;

    const int am  = tid >> 2;
    const int akc = (tid & 3) * 4;
    const float* asrc0 = g_H + ((size_t)e*CAP + (size_t)mt*128 + am) * DFF + akc;
    const float* asrc1 = asrc0 + (size_t)64 * DFF;

    const int bk = tid >> 5;             // rows bk, bk+8
    const int bn = (tid & 31) * 4;
    const float* bsrc0 = Wd + (size_t)e*DFF*DMODEL + (size_t)bk*DMODEL + (size_t)nt*128 + bn;
    const float* bsrc1 = bsrc0 + (size_t)8 * DMODEL;

    const unsigned a_lo = (((lane & 7) + ((lane >> 3) & 1) * 8) * AS_STR
                          + ((lane >> 4) << 2)) * 4u;
    const unsigned asb0 = smem_u32(&As[0][0]);
    const unsigned asb1 = smem_u32(&As[1][0]);

    float4 ra0, ra1, rb0, rb1;
    float c[4][4][4];
    #pragma unroll
    for (int i = 0; i < 4; i++)
        #pragma unroll
        for (int j = 0; j < 4; j++)
            #pragma unroll
            for (int r = 0; r < 4; r++) c[i][j][r] = 0.f;

#define G2_LOAD(kt) do {                                                      \
        ra0 = *(const float4*)(asrc0 + (size_t)(kt)*16);                       \
        ra1 = *(const float4*)(asrc1 + (size_t)(kt)*16);                       \
        rb0 = *(const float4*)(bsrc0 + (size_t)(kt)*16*DMODEL);                \
        rb1 = *(const float4*)(bsrc1 + (size_t)(kt)*16*DMODEL);                \
    } while (0)
#define G2_STORE(s) do {                                                      \
        unsigned* Ad = As[s];                                                 \
        Ad[am*AS_STR + akc + 0] = f2tf(ra0.x); Ad[am*AS_STR + akc + 1] = f2tf(ra0.y); \
        Ad[am*AS_STR + akc + 2] = f2tf(ra0.z); Ad[am*AS_STR + akc + 3] = f2tf(ra0.w); \
        Ad[(am+64)*AS_STR + akc + 0] = f2tf(ra1.x);                           \
        Ad[(am+64)*AS_STR + akc + 1] = f2tf(ra1.y);                           \
        Ad[(am+64)*AS_STR + akc + 2] = f2tf(ra1.z);                           \
        Ad[(am+64)*AS_STR + akc + 3] = f2tf(ra1.w);                           \
        unsigned* B0 = &Bs[s][bk*132 + bn];                                   \
        B0[0] = f2tf(rb0.x); B0[1] = f2tf(rb0.y); B0[2] = f2tf(rb0.z); B0[3] = f2tf(rb0.w); \
        unsigned* B1 = &Bs[s][(bk+8)*132 + bn];                               \
        B1[0] = f2tf(rb1.x); B1[1] = f2tf(rb1.y); B1[2] = f2tf(rb1.z); B1[3] = f2tf(rb1.w); \
    } while (0)

    G2_LOAD(0);
    G2_STORE(0);
    __syncthreads();

    const int NKT = DFF / 16;
    for (int kt = 0; kt < NKT; kt++) {
        if (kt + 1 < NKT) G2_LOAD(kt + 1);
        const int s = kt & 1;
        const unsigned asb = s ? asb1 : asb0;
        #pragma unroll
        for (int kk = 0; kk < 16; kk += 8) {
            unsigned a[4][4], b[4][2];
            const unsigned ab = asb + (unsigned)(wmb * (AS_STR*4)) + (unsigned)(kk*4) + a_lo;
            #pragma unroll
            for (int mf = 0; mf < 4; mf++)
                ldsm4(a[mf], ab + (unsigned)(mf * 16 * (AS_STR*4)));
            #pragma unroll
            for (int nf = 0; nf < 4; nf++) {
                int nc = wnb + nf*8 + gid;
                b[nf][0] = Bs[s][(kk+tig  )*132 + nc];
                b[nf][1] = Bs[s][(kk+tig+4)*132 + nc];
            }
            #pragma unroll
            for (int mf = 0; mf < 4; mf++)
                #pragma unroll
                for (int nf = 0; nf < 4; nf++)
                    mma_tf32(c[mf][nf], a[mf], b[nf]);
        }
        if (kt + 1 < NKT) G2_STORE((kt + 1) & 1);
        __syncthreads();
    }

    float* Obase = g_O + ((size_t)e*CAP + (size_t)mt*128) * DMODEL + (size_t)nt*128;
    #pragma unroll
    for (int mf = 0; mf < 4; mf++) {
        #pragma unroll
        for (int nf = 0; nf < 4; nf++) {
            int r0 = wmb + mf*16 + gid;
            int c0 = wnb + nf*8 + tig*2;
            float* p0 = Obase + (size_t)r0 * DMODEL + c0;
            float* p1 = Obase + (size_t)(r0 + 8) * DMODEL + c0;
            p0[0] = c[mf][nf][0]; p0[1] = c[mf][nf][1];
            p1[0] = c[mf][nf][2]; p1[1] = c[mf][nf][3];
        }
    }
#undef G2_LOAD
#undef G2_STORE
}

// ---------------------------------------------------------------------------
// Kernel 4: combine.  out[t] = v0*O[e0][r0] + v1*O[e1][r1]
// ---------------------------------------------------------------------------
__global__ void combine_kernel(float* __restrict__ out) {
    const int t  = blockIdx.x;
    const int e0 = g_tok_e[2*t + 0], e1 = g_tok_e[2*t + 1];
    const int r0 = g_tok_r[2*t + 0], r1 = g_tok_r[2*t + 1];
    const float v0 = g_tok_v[2*t + 0], v1 = g_tok_v[2*t + 1];
    const float4* o0 = (const float4*)(g_O + ((size_t)e0*CAP + r0) * DMODEL);
    const float4* o1 = (const float4*)(g_O + ((size_t)e1*CAP + r1) * DMODEL);
    float4* dst = (float4*)(out + (size_t)t * DMODEL);
    for (int i = threadIdx.x; i < DMODEL / 4; i += blockDim.x) {
        float4 a = o0[i], b = o1[i];
        float4 r;
        r.x = v0 * a.x + v1 * b.x;
        r.y = v0 * a.y + v1 * b.y;
        r.z = v0 * a.z + v1 * b.z;
        r.w = v0 * a.w + v1 * b.w;
        dst[i] = r;
    }
}

// ---------------------------------------------------------------------------
// Launch
// ---------------------------------------------------------------------------
extern "C" void kernel_launch(void* const* d_in, const int* in_sizes, int n_in,
                              void* d_out, int out_size) {
    const float* x  = (const float*)d_in[0];   // [B,S,D]
    const float* Wr = (const float*)d_in[1];   // [D,E]
    const float* Wg = (const float*)d_in[2];   // [E,D,F]
    const float* Wu = (const float*)d_in[3];   // [E,D,F]
    const float* Wd = (const float*)d_in[4];   // [E,F,D]
    float* out = (float*)d_out;                // [B,S,D]

    init_kernel<<<1, 32>>>();
    router_kernel<<<NTOK, 128>>>(x, Wr);

    // mt fastest: concurrent blocks share the same B tile through L2,
    // so Wg/Wu stream from DRAM once instead of once per mt-pass.
    dim3 grid1(CAP / 128, DFF / 64, NEXP);     // (16, 128, 4)
    gemm1_kernel<<<grid1, 256>>>(x, Wg, Wu);

    dim3 grid2(DMODEL / 128, CAP / 128, NEXP); // (16, 16, 4)
    gemm2_kernel<<<grid2, 256>>>(Wd);

    combine_kernel<<<NTOK, 256>>>(out);
}

// round 12
// speedup vs baseline: 1.4069x; 1.4069x over previous
#include <cuda_runtime.h>
#include <cstdint>
#include <cstddef>

// Problem constants
#define NTOK   2048
#define DMODEL 2048
#define DFF    8192
#define NEXP   4
#define CAP    2048
#define AS_STR 20                  // padded A row stride (floats) for ldmatrix

// Pipeline
#define KT     16                  // K elems per stage
#define NS     4                   // stages

// gemm1 stage layout (bytes within one stage)
#define G1_A   0
#define G1_BG  10240               // 128*AS_STR*4
#define G1_BU  (G1_BG + 16*68*4)   // 14592
#define G1_STG (G1_BU + 16*68*4)   // 18944
#define G1_SMEM (NS * G1_STG)      // 75776

// gemm2 stage layout
#define G2_A   0
#define G2_B   10240
#define G2_STG (G2_B + 16*132*4)   // 18688
#define G2_SMEM (NS * G2_STG)      // 74752

// ---------------------------------------------------------------------------
// Scratch (static device globals; no allocation anywhere)
// ---------------------------------------------------------------------------
__device__ int   g_cnt[NEXP];
__device__ int   g_list[NEXP * CAP];
__device__ int   g_tok_e[NTOK * 2];
__device__ int   g_tok_r[NTOK * 2];
__device__ float g_tok_v[NTOK * 2];
__device__ __align__(256) float g_H[(size_t)NEXP * CAP * DFF];       // 268 MB (tf32-rounded)
__device__ __align__(256) float g_O[(size_t)NEXP * CAP * DMODEL];    //  67 MB
__device__ __align__(256) float g_xc [(size_t)NTOK * DMODEL];        //  16 MB (tf32-rounded x)
__device__ __align__(256) float g_Wgc[(size_t)NEXP * DMODEL * DFF];  // 256 MB
__device__ __align__(256) float g_Wuc[(size_t)NEXP * DMODEL * DFF];  // 256 MB
__device__ __align__(256) float g_Wdc[(size_t)NEXP * DFF * DMODEL];  // 256 MB

// ---------------------------------------------------------------------------
// PTX helpers
// ---------------------------------------------------------------------------
__device__ __forceinline__ unsigned f2tf(float x) {
    unsigned u;
    asm("cvt.rna.tf32.f32 %0, %1;" : "=r"(u) : "f"(x));
    return u;
}

__device__ __forceinline__ void mma_tf32(float* c, const unsigned* a, const unsigned* b) {
    asm volatile(
        "mma.sync.aligned.m16n8k8.row.col.f32.tf32.tf32.f32 "
        "{%0,%1,%2,%3}, {%4,%5,%6,%7}, {%8,%9}, {%0,%1,%2,%3};"
        : "+f"(c[0]), "+f"(c[1]), "+f"(c[2]), "+f"(c[3])
        : "r"(a[0]), "r"(a[1]), "r"(a[2]), "r"(a[3]), "r"(b[0]), "r"(b[1]));
}

// ldmatrix.x4 on tf32 data viewed as b16 pairs == exact tf32 A-fragment layout.
__device__ __forceinline__ void ldsm4(unsigned* r, unsigned addr) {
    asm volatile("ldmatrix.sync.aligned.m8n8.x4.shared.b16 {%0,%1,%2,%3}, [%4];"
        : "=r"(r[0]), "=r"(r[1]), "=r"(r[2]), "=r"(r[3]) : "r"(addr));
}

__device__ __forceinline__ unsigned smem_u32(const void* p) {
    return (unsigned)__cvta_generic_to_shared(p);
}

// 16B async copy with zero-fill when pred is false
#define CPA(dst, src, p) \
    asm volatile("cp.async.cg.shared.global [%0], [%1], 16, %2;" \
        :: "r"(dst), "l"(src), "r"((p) ? 16 : 0) : "memory")
#define CPA_COMMIT() asm volatile("cp.async.commit_group;" ::: "memory")
#define CPA_WAIT2()  asm volatile("cp.async.wait_group 2;" ::: "memory")

// ---------------------------------------------------------------------------
// Kernel 0: reset per-expert counters
// ---------------------------------------------------------------------------
__global__ void init_kernel() {
    if (threadIdx.x < NEXP) g_cnt[threadIdx.x] = 0;
}

// ---------------------------------------------------------------------------
// Kernel C: elementwise tf32 (rna) rounding  out[i] = tf32(in[i])
// ---------------------------------------------------------------------------
__global__ void cvt_kernel(const float4* __restrict__ in, float4* __restrict__ out, int n4) {
    int stride = gridDim.x * blockDim.x;
    for (int i = blockIdx.x * blockDim.x + threadIdx.x; i < n4; i += stride) {
        float4 v = in[i];
        float4 r;
        r.x = __uint_as_float(f2tf(v.x));
        r.y = __uint_as_float(f2tf(v.y));
        r.z = __uint_as_float(f2tf(v.z));
        r.w = __uint_as_float(f2tf(v.w));
        out[i] = r;
    }
}

// ---------------------------------------------------------------------------
// Kernel 1: router
// ---------------------------------------------------------------------------
__global__ void router_kernel(const float* __restrict__ x, const float* __restrict__ Wr) {
    const int t = blockIdx.x;
    const float* xr = x + (size_t)t * DMODEL;

    float a0 = 0.f, a1 = 0.f, a2 = 0.f, a3 = 0.f;
    for (int d = threadIdx.x; d < DMODEL; d += 128) {
        float xv = xr[d];
        const float* w = Wr + d * NEXP;
        a0 += xv * w[0]; a1 += xv * w[1]; a2 += xv * w[2]; a3 += xv * w[3];
    }
    #pragma unroll
    for (int o = 16; o > 0; o >>= 1) {
        a0 += __shfl_xor_sync(0xffffffffu, a0, o);
        a1 += __shfl_xor_sync(0xffffffffu, a1, o);
        a2 += __shfl_xor_sync(0xffffffffu, a2, o);
        a3 += __shfl_xor_sync(0xffffffffu, a3, o);
    }
    __shared__ float red[4][NEXP];
    const int warp = threadIdx.x >> 5;
    if ((threadIdx.x & 31) == 0) {
        red[warp][0] = a0; red[warp][1] = a1; red[warp][2] = a2; red[warp][3] = a3;
    }
    __syncthreads();
    if (threadIdx.x == 0) {
        float l[NEXP];
        #pragma unroll
        for (int e = 0; e < NEXP; e++)
            l[e] = red[0][e] + red[1][e] + red[2][e] + red[3][e];
        float mx = l[0];
        #pragma unroll
        for (int e = 1; e < NEXP; e++) mx = fmaxf(mx, l[e]);
        float p[NEXP]; float s = 0.f;
        #pragma unroll
        for (int e = 0; e < NEXP; e++) { p[e] = __expf(l[e] - mx); s += p[e]; }
        float inv = 1.f / s;
        #pragma unroll
        for (int e = 0; e < NEXP; e++) p[e] *= inv;
        int e0 = 0;
        #pragma unroll
        for (int e = 1; e < NEXP; e++) if (p[e] > p[e0]) e0 = e;
        int e1 = (e0 == 0) ? 1 : 0;
        #pragma unroll
        for (int e = 0; e < NEXP; e++) if (e != e0 && p[e] > p[e1]) e1 = e;

        int s0 = atomicAdd(&g_cnt[e0], 1);
        g_list[e0 * CAP + s0] = t;
        g_tok_e[2*t + 0] = e0; g_tok_r[2*t + 0] = s0; g_tok_v[2*t + 0] = p[e0];

        int s1 = atomicAdd(&g_cnt[e1], 1);
        g_list[e1 * CAP + s1] = t;
        g_tok_e[2*t + 1] = e1; g_tok_r[2*t + 1] = s1; g_tok_v[2*t + 1] = p[e1];
    }
}

// ---------------------------------------------------------------------------
// Kernel 2: fused dual GEMM, cp.async 4-stage pipeline.
// Tile 128(M)x64(N)x16(K); 8 warps (4M x 2N), warp tile 32x32.
// g = gather(xc) @ Wgc, u = gather(xc) @ Wuc; H = tf32(silu(g)*u).
// ---------------------------------------------------------------------------
__global__ __launch_bounds__(256, 2) void gemm1_kernel() {
    const int e   = blockIdx.z;
    const int mt  = blockIdx.x;   // fastest: all mt concurrent -> B streamed once
    const int nt  = blockIdx.y;
    const int cnt = g_cnt[e];
    if (mt * 128 >= cnt) return;

    extern __shared__ char smem[];
    const unsigned sb = smem_u32(smem);

    const int tid  = threadIdx.x;
    const int lane = tid & 31;
    const int warp = tid >> 5;
    const int gid  = lane >> 2;
    const int tig  = lane & 3;
    const int wmb  = (warp & 3) * 32;
    const int wnb  = (warp >> 2) * 32;

    // producer mapping
    const int arow = tid >> 1;             // 0..127
    const int ach  = (tid & 1) * 2;        // chunk pair 0-1 / 2-3
    const int m    = mt * 128 + arow;
    const bool ap  = (m < cnt);
    const float* asrc = ap ? (g_xc + (size_t)g_list[e*CAP + m] * DMODEL + ach*4) : g_xc;
    const unsigned a_d = (unsigned)(arow * (AS_STR*4) + ach*16);

    const int brow = tid >> 4;             // 0..15
    const int bch  = tid & 15;             // 16B chunk in 64-float row
    const float* bgsrc = g_Wgc + (size_t)e*DMODEL*DFF + (size_t)brow*DFF + (size_t)nt*64 + bch*4;
    const float* busrc = g_Wuc + (size_t)e*DMODEL*DFF + (size_t)brow*DFF + (size_t)nt*64 + bch*4;
    const unsigned b_d = (unsigned)(brow * 272 + bch*16);

    const unsigned a_lo = (((lane & 7) + ((lane >> 3) & 1) * 8) * AS_STR) * 4u
                        + ((lane >> 4) << 4);

    float cg[2][4][4], cu[2][4][4];
    #pragma unroll
    for (int i = 0; i < 2; i++)
        #pragma unroll
        for (int j = 0; j < 4; j++)
            #pragma unroll
            for (int r = 0; r < 4; r++) { cg[i][j][r] = 0.f; cu[i][j][r] = 0.f; }

#define G1_ISSUE(kt, slot) do {                                              \
        unsigned base = sb + (slot) * G1_STG;                                \
        const float* as_ = asrc + (size_t)(kt) * KT;                         \
        CPA(base + a_d,      as_,     ap);                                   \
        CPA(base + a_d + 16, as_ + 4, ap);                                   \
        CPA(base + G1_BG + b_d, bgsrc + (size_t)(kt)*KT*DFF, true);          \
        CPA(base + G1_BU + b_d, busrc + (size_t)(kt)*KT*DFF, true);          \
        CPA_COMMIT();                                                        \
    } while (0)

    const int NKT = DMODEL / KT;   // 128
    G1_ISSUE(0, 0); G1_ISSUE(1, 1); G1_ISSUE(2, 2);

    for (int kt = 0; kt < NKT; kt++) {
        CPA_WAIT2();
        __syncthreads();
        if (kt + NS - 1 < NKT) G1_ISSUE(kt + NS - 1, (kt + NS - 1) & (NS - 1));
        else CPA_COMMIT();

        const int slot = kt & (NS - 1);
        const unsigned abase = sb + slot * G1_STG + (unsigned)(wmb * (AS_STR*4)) + a_lo;
        const float* Bg = (const float*)(smem + slot * G1_STG + G1_BG);
        const float* Bu = (const float*)(smem + slot * G1_STG + G1_BU);

        #pragma unroll
        for (int kk = 0; kk < KT; kk += 8) {
            unsigned a[2][4], bG[4][2], bU[4][2];
            ldsm4(a[0], abase + (unsigned)(kk*4));
            ldsm4(a[1], abase + (unsigned)(kk*4) + 16u * (AS_STR*4));
            #pragma unroll
            for (int nf = 0; nf < 4; nf++) {
                int nc = wnb + nf*8 + gid;
                bG[nf][0] = __float_as_uint(Bg[(kk+tig  )*68 + nc]);
                bG[nf][1] = __float_as_uint(Bg[(kk+tig+4)*68 + nc]);
                bU[nf][0] = __float_as_uint(Bu[(kk+tig  )*68 + nc]);
                bU[nf][1] = __float_as_uint(Bu[(kk+tig+4)*68 + nc]);
            }
            #pragma unroll
            for (int mf = 0; mf < 2; mf++)
                #pragma unroll
                for (int nf = 0; nf < 4; nf++) {
                    mma_tf32(cg[mf][nf], a[mf], bG[nf]);
                    mma_tf32(cu[mf][nf], a[mf], bU[nf]);
                }
        }
    }
#undef G1_ISSUE

    // epilogue: H = tf32(silu(g) * u); padded rows produce exactly 0.
    float* Hbase = g_H + ((size_t)e*CAP + (size_t)mt*128) * DFF + (size_t)nt*64;
    #pragma unroll
    for (int mf = 0; mf < 2; mf++) {
        #pragma unroll
        for (int nf = 0; nf < 4; nf++) {
            int r0 = wmb + mf*16 + gid;
            int c0 = wnb + nf*8 + tig*2;
            float* p0 = Hbase + (size_t)r0 * DFF + c0;
            float* p1 = Hbase + (size_t)(r0 + 8) * DFF + c0;
            float g0 = cg[mf][nf][0], g1 = cg[mf][nf][1];
            float g2 = cg[mf][nf][2], g3 = cg[mf][nf][3];
            p0[0] = __uint_as_float(f2tf((g0 / (1.f + __expf(-g0))) * cu[mf][nf][0]));
            p0[1] = __uint_as_float(f2tf((g1 / (1.f + __expf(-g1))) * cu[mf][nf][1]));
            p1[0] = __uint_as_float(f2tf((g2 / (1.f + __expf(-g2))) * cu[mf][nf][2]));
            p1[1] = __uint_as_float(f2tf((g3 / (1.f + __expf(-g3))) * cu[mf][nf][3]));
        }
    }
}

// ---------------------------------------------------------------------------
// Kernel 3: O = H @ Wdc, cp.async 4-stage pipeline.
// Tile 128(M)x128(N)x16(K); 8 warps (2M x 4N), warp tile 64x32.
// ---------------------------------------------------------------------------
__global__ __launch_bounds__(256, 2) void gemm2_kernel() {
    const int e   = blockIdx.z;
    const int mt  = blockIdx.x;   // fastest
    const int nt  = blockIdx.y;
    const int cnt = g_cnt[e];
    if (mt * 128 >= cnt) return;

    extern __shared__ char smem[];
    const unsigned sb = smem_u32(smem);

    const int tid  = threadIdx.x;
    const int lane = tid & 31;
    const int warp = tid >> 5;
    const int gid  = lane >> 2;
    const int tig  = lane & 3;
    const int wmb  = (warp & 1) * 64;
    const int wnb  = (warp >> 1) * 32;

    const int arow = tid >> 1;
    const int ach  = (tid & 1) * 2;
    const float* asrc = g_H + ((size_t)e*CAP + (size_t)mt*128 + arow) * DFF + ach*4;
    const unsigned a_d = (unsigned)(arow * (AS_STR*4) + ach*16);

    const int brow = tid >> 4;             // 0..15
    const int bch  = (tid & 15) * 2;       // chunk pair in 128-float row
    const float* bsrc = g_Wdc + ((size_t)e*DFF + brow) * DMODEL + (size_t)nt*128 + bch*4;
    const unsigned b_d = (unsigned)(brow * 528 + bch*16);

    const unsigned a_lo = (((lane & 7) + ((lane >> 3) & 1) * 8) * AS_STR) * 4u
                        + ((lane >> 4) << 4);

    float c[4][4][4];
    #pragma unroll
    for (int i = 0; i < 4; i++)
        #pragma unroll
        for (int j = 0; j < 4; j++)
            #pragma unroll
            for (int r = 0; r < 4; r++) c[i][j][r] = 0.f;

#define G2_ISSUE(kt, slot) do {                                              \
        unsigned base = sb + (slot) * G2_STG;                                \
        const float* as_ = asrc + (size_t)(kt) * KT;                         \
        CPA(base + a_d,      as_,     true);                                 \
        CPA(base + a_d + 16, as_ + 4, true);                                 \
        const float* bs_ = bsrc + (size_t)(kt)*KT*DMODEL;                    \
        CPA(base + G2_B + b_d,      bs_,     true);                          \
        CPA(base + G2_B + b_d + 16, bs_ + 4, true);                          \
        CPA_COMMIT();                                                        \
    } while (0)

    const int NKT = DFF / KT;   // 512
    G2_ISSUE(0, 0); G2_ISSUE(1, 1); G2_ISSUE(2, 2);

    for (int kt = 0; kt < NKT; kt++) {
        CPA_WAIT2();
        __syncthreads();
        if (kt + NS - 1 < NKT) G2_ISSUE(kt + NS - 1, (kt + NS - 1) & (NS - 1));
        else CPA_COMMIT();

        const int slot = kt & (NS - 1);
        const unsigned abase = sb + slot * G2_STG + (unsigned)(wmb * (AS_STR*4)) + a_lo;
        const float* Bs = (const float*)(smem + slot * G2_STG + G2_B);

        #pragma unroll
        for (int kk = 0; kk < KT; kk += 8) {
            unsigned a[4][4], b[4][2];
            #pragma unroll
            for (int mf = 0; mf < 4; mf++)
                ldsm4(a[mf], abase + (unsigned)(kk*4) + (unsigned)(mf * 16 * (AS_STR*4)));
            #pragma unroll
            for (int nf = 0; nf < 4; nf++) {
                int nc = wnb + nf*8 + gid;
                b[nf][0] = __float_as_uint(Bs[(kk+tig  )*132 + nc]);
                b[nf][1] = __float_as_uint(Bs[(kk+tig+4)*132 + nc]);
            }
            #pragma unroll
            for (int mf = 0; mf < 4; mf++)
                #pragma unroll
                for (int nf = 0; nf < 4; nf++)
                    mma_tf32(c[mf][nf], a[mf], b[nf]);
        }
    }
#undef G2_ISSUE

    float* Obase = g_O + ((size_t)e*CAP + (size_t)mt*128) * DMODEL + (size_t)nt*128;
    #pragma unroll
    for (int mf = 0; mf < 4; mf++) {
        #pragma unroll
        for (int nf = 0; nf < 4; nf++) {
            int r0 = wmb + mf*16 + gid;
            int c0 = wnb + nf*8 + tig*2;
            float* p0 = Obase + (size_t)r0 * DMODEL + c0;
            float* p1 = Obase + (size_t)(r0 + 8) * DMODEL + c0;
            p0[0] = c[mf][nf][0]; p0[1] = c[mf][nf][1];
            p1[0] = c[mf][nf][2]; p1[1] = c[mf][nf][3];
        }
    }
}

// ---------------------------------------------------------------------------
// Kernel 4: combine.  out[t] = v0*O[e0][r0] + v1*O[e1][r1]
// ---------------------------------------------------------------------------
__global__ void combine_kernel(float* __restrict__ out) {
    const int t  = blockIdx.x;
    const int e0 = g_tok_e[2*t + 0], e1 = g_tok_e[2*t + 1];
    const int r0 = g_tok_r[2*t + 0], r1 = g_tok_r[2*t + 1];
    const float v0 = g_tok_v[2*t + 0], v1 = g_tok_v[2*t + 1];
    const float4* o0 = (const float4*)(g_O + ((size_t)e0*CAP + r0) * DMODEL);
    const float4* o1 = (const float4*)(g_O + ((size_t)e1*CAP + r1) * DMODEL);
    float4* dst = (float4*)(out + (size_t)t * DMODEL);
    for (int i = threadIdx.x; i < DMODEL / 4; i += blockDim.x) {
        float4 a = o0[i], b = o1[i];
        float4 r;
        r.x = v0 * a.x + v1 * b.x;
        r.y = v0 * a.y + v1 * b.y;
        r.z = v0 * a.z + v1 * b.z;
        r.w = v0 * a.w + v1 * b.w;
        dst[i] = r;
    }
}

// ---------------------------------------------------------------------------
// Launch
// ---------------------------------------------------------------------------
extern "C" void kernel_launch(void* const* d_in, const int* in_sizes, int n_in,
                              void* d_out, int out_size) {
    const float* x  = (const float*)d_in[0];
    const float* Wr = (const float*)d_in[1];
    const float* Wg = (const float*)d_in[2];   // [E,D,F]
    const float* Wu = (const float*)d_in[3];   // [E,D,F]
    const float* Wd = (const float*)d_in[4];   // [E,F,D]
    float* out = (float*)d_out;

    cudaFuncSetAttribute(gemm1_kernel, cudaFuncAttributeMaxDynamicSharedMemorySize, G1_SMEM);
    cudaFuncSetAttribute(gemm2_kernel, cudaFuncAttributeMaxDynamicSharedMemorySize, G2_SMEM);

    float *xc, *wgc, *wuc, *wdc;
    cudaGetSymbolAddress((void**)&xc,  g_xc);
    cudaGetSymbolAddress((void**)&wgc, g_Wgc);
    cudaGetSymbolAddress((void**)&wuc, g_Wuc);
    cudaGetSymbolAddress((void**)&wdc, g_Wdc);

    init_kernel<<<1, 32>>>();
    router_kernel<<<NTOK, 128>>>(x, Wr);

    // tf32 (rna) pre-rounding of x and all expert weights
    const int nW4 = (int)((size_t)NEXP * DMODEL * DFF / 4);   // 16,777,216
    const int nX4 = NTOK * DMODEL / 4;                        //  1,048,576
    cvt_kernel<<<4096, 256>>>((const float4*)x,  (float4*)xc,  nX4);
    cvt_kernel<<<8192, 256>>>((const float4*)Wg, (float4*)wgc, nW4);
    cvt_kernel<<<8192, 256>>>((const float4*)Wu, (float4*)wuc, nW4);
    cvt_kernel<<<8192, 256>>>((const float4*)Wd, (float4*)wdc, nW4);

    // mt fastest: one wave spans all M tiles -> each B tile streamed from DRAM once
    dim3 grid1(CAP / 128, DFF / 64, NEXP);     // (16, 128, 4)
    gemm1_kernel<<<grid1, 256, G1_SMEM>>>();

    dim3 grid2(CAP / 128, DMODEL / 128, NEXP); // (16, 16, 4)
    gemm2_kernel<<<grid2, 256, G2_SMEM>>>();

    combine_kernel<<<NTOK, 256>>>(out);
}